// round 1
// baseline (speedup 1.0000x reference)
#include <cuda_runtime.h>
#include <cuda_bf16.h>

#define SEQ      4096
#define DIM      768
#define NH       12
#define HD       64
#define QKVDIM   2304
#define WIN      64      // WINDOW/2

// ---------------- scratch (device globals; no allocation allowed) -----------
__device__ float g_qkv[SEQ * QKVDIM];          // [s][e]
__device__ float g_q  [NH * SEQ * HD];         // [h][s][d]  (RoPE'd, pre-scaled)
__device__ float g_k  [NH * SEQ * HD];         // [h][s][d]  (RoPE'd)
__device__ float g_v  [NH * SEQ * HD];         // [h][s][d]
__device__ float g_ao [SEQ * DIM];             // [s][h*64+d]

// ---------------- 128x128x8 SGEMM, C[m,n] = sum_k A[m,k]*B[n,k] -------------
// A: row-major [M,K], B: row-major [N,K]. M,N % 128 == 0, K % 8 == 0.
__global__ void __launch_bounds__(256) gemm_nt_kernel(
    const float* __restrict__ A, const float* __restrict__ B,
    float* __restrict__ C, int M, int N, int K)
{
    __shared__ float sA[8][132];
    __shared__ float sB[8][132];

    const int tid = threadIdx.x;
    const int m0 = blockIdx.y * 128;
    const int n0 = blockIdx.x * 128;
    const int tx = tid & 15;        // 0..15
    const int ty = tid >> 4;        // 0..15

    const int lr = tid >> 1;        // 0..127
    const int lc = (tid & 1) * 4;   // 0 or 4

    const float* Aptr = A + (size_t)(m0 + lr) * K + lc;
    const float* Bptr = B + (size_t)(n0 + lr) * K + lc;

    float acc[8][8];
#pragma unroll
    for (int i = 0; i < 8; i++)
#pragma unroll
        for (int j = 0; j < 8; j++) acc[i][j] = 0.f;

    for (int k0 = 0; k0 < K; k0 += 8) {
        float4 a4 = *(const float4*)(Aptr + k0);
        float4 b4 = *(const float4*)(Bptr + k0);
        __syncthreads();
        sA[lc + 0][lr] = a4.x; sA[lc + 1][lr] = a4.y;
        sA[lc + 2][lr] = a4.z; sA[lc + 3][lr] = a4.w;
        sB[lc + 0][lr] = b4.x; sB[lc + 1][lr] = b4.y;
        sB[lc + 2][lr] = b4.z; sB[lc + 3][lr] = b4.w;
        __syncthreads();
#pragma unroll
        for (int kk = 0; kk < 8; kk++) {
            float ar[8], br[8];
            *(float4*)(ar)     = *(const float4*)&sA[kk][ty * 8];
            *(float4*)(ar + 4) = *(const float4*)&sA[kk][ty * 8 + 4];
            *(float4*)(br)     = *(const float4*)&sB[kk][tx * 8];
            *(float4*)(br + 4) = *(const float4*)&sB[kk][tx * 8 + 4];
#pragma unroll
            for (int i = 0; i < 8; i++)
#pragma unroll
                for (int j = 0; j < 8; j++)
                    acc[i][j] += ar[i] * br[j];
        }
    }

#pragma unroll
    for (int i = 0; i < 8; i++) {
        float* Crow = C + (size_t)(m0 + ty * 8 + i) * N + n0 + tx * 8;
        *(float4*)(Crow)     = make_float4(acc[i][0], acc[i][1], acc[i][2], acc[i][3]);
        *(float4*)(Crow + 4) = make_float4(acc[i][4], acc[i][5], acc[i][6], acc[i][7]);
    }
}

// ---------------- split qkv + RoPE + transpose to [h][s][d] -----------------
__global__ void rope_split_kernel(const int* __restrict__ pos_ids)
{
    int idx = blockIdx.x * blockDim.x + threadIdx.x;   // over SEQ*NH*32
    if (idx >= SEQ * NH * 32) return;
    int i = idx & 31;
    int h = (idx >> 5) % NH;
    int s = idx / (32 * NH);

    float pos = (float)pos_ids[s];
    // inv_freq = theta^(-i/32)
    float inv = powf(10000.0f, -(float)i / 32.0f);
    float f = pos * inv;
    float c = cosf(f), sn = sinf(f);

    const float* row = g_qkv + (size_t)s * QKVDIM;
    int base = (h * SEQ + s) * HD;

    // q (fold softmax scale 1/8 into q)
    float q1 = row[h * HD + i], q2 = row[h * HD + i + 32];
    g_q[base + i]      = (q1 * c - q2 * sn) * 0.125f;
    g_q[base + i + 32] = (q2 * c + q1 * sn) * 0.125f;
    // k
    float k1 = row[DIM + h * HD + i], k2 = row[DIM + h * HD + i + 32];
    g_k[base + i]      = k1 * c - k2 * sn;
    g_k[base + i + 32] = k2 * c + k1 * sn;
    // v
    g_v[base + i]      = row[2 * DIM + h * HD + i];
    g_v[base + i + 32] = row[2 * DIM + h * HD + i + 32];
}

// ---------------- sliding-window attention ----------------------------------
// block = (q-tile of 128, head). 1 thread per query, online softmax.
#define QT   128
#define KT   256              // QT + 2*WIN
#define KPAD 68               // row pad -> conflict-free float4 LDS
__global__ void __launch_bounds__(128) attn_kernel()
{
    extern __shared__ float smem[];
    float* sK = smem;                  // [KT][KPAD]
    float* sV = smem + KT * KPAD;      // [KT][KPAD]

    const int h    = blockIdx.y;
    const int tile = blockIdx.x;
    const int q    = tile * QT + threadIdx.x;
    const int kbase = tile * QT - WIN;

    const float* Kh = g_k + (size_t)h * SEQ * HD;
    const float* Vh = g_v + (size_t)h * SEQ * HD;

    // stage K,V tiles (float4, coalesced)
    for (int t = threadIdx.x; t < KT * (HD / 4); t += QT) {
        int r  = t >> 4;          // key row in tile
        int c4 = t & 15;          // float4 column
        int gr = kbase + r;
        if (gr >= 0 && gr < SEQ) {
            *(float4*)(sK + r * KPAD + c4 * 4) = *(const float4*)(Kh + (size_t)gr * HD + c4 * 4);
            *(float4*)(sV + r * KPAD + c4 * 4) = *(const float4*)(Vh + (size_t)gr * HD + c4 * 4);
        }
    }
    __syncthreads();

    float qr[HD];
    const float* Qp = g_q + ((size_t)h * SEQ + q) * HD;
#pragma unroll
    for (int d = 0; d < HD; d++) qr[d] = Qp[d];

    float m = -1e30f, l = 0.f;
    float acc[HD];
#pragma unroll
    for (int d = 0; d < HD; d++) acc[d] = 0.f;

    const int lo = (q - WIN < 0) ? 0 : q - WIN;
    const int hi = (q + WIN > SEQ - 1) ? SEQ - 1 : q + WIN;

    for (int j = lo; j <= hi; j++) {
        const float* kr = sK + (j - kbase) * KPAD;
        float s = 0.f;
#pragma unroll
        for (int d4 = 0; d4 < HD / 4; d4++) {
            float4 kk = *(const float4*)(kr + 4 * d4);
            s += qr[4 * d4 + 0] * kk.x + qr[4 * d4 + 1] * kk.y
               + qr[4 * d4 + 2] * kk.z + qr[4 * d4 + 3] * kk.w;
        }
        if (s > m) {
            float corr = __expf(m - s);
            m = s;
            l *= corr;
#pragma unroll
            for (int d = 0; d < HD; d++) acc[d] *= corr;
        }
        float e = __expf(s - m);
        l += e;
        const float* vr = sV + (j - kbase) * KPAD;
#pragma unroll
        for (int d4 = 0; d4 < HD / 4; d4++) {
            float4 vv = *(const float4*)(vr + 4 * d4);
            acc[4 * d4 + 0] += e * vv.x;
            acc[4 * d4 + 1] += e * vv.y;
            acc[4 * d4 + 2] += e * vv.z;
            acc[4 * d4 + 3] += e * vv.w;
        }
    }

    float invl = 1.f / l;
    float* op = g_ao + (size_t)q * DIM + h * HD;
#pragma unroll
    for (int d4 = 0; d4 < HD / 4; d4++) {
        float4 o;
        o.x = acc[4 * d4 + 0] * invl;
        o.y = acc[4 * d4 + 1] * invl;
        o.z = acc[4 * d4 + 2] * invl;
        o.w = acc[4 * d4 + 3] * invl;
        *(float4*)(op + 4 * d4) = o;
    }
}

// ---------------- launch -----------------------------------------------------
extern "C" void kernel_launch(void* const* d_in, const int* in_sizes, int n_in,
                              void* d_out, int out_size)
{
    const float* x    = (const float*)d_in[0];
    const int*   pos  = (const int*)  d_in[1];
    const float* wqkv = (const float*)d_in[2];
    const float* wo   = (const float*)d_in[3];
    float*       out  = (float*)d_out;

    float *pqkv, *pao;
    cudaGetSymbolAddress((void**)&pqkv, g_qkv);
    cudaGetSymbolAddress((void**)&pao,  g_ao);

    // 1) QKV projection: [4096,768] x [2304,768]^T -> [4096,2304]
    gemm_nt_kernel<<<dim3(QKVDIM / 128, SEQ / 128), 256>>>(x, wqkv, pqkv, SEQ, QKVDIM, DIM);

    // 2) split + RoPE + transpose
    {
        int total = SEQ * NH * 32;
        rope_split_kernel<<<(total + 255) / 256, 256>>>(pos);
    }

    // 3) sliding-window attention
    {
        size_t smem = (size_t)2 * KT * KPAD * sizeof(float);   // ~139 KB
        cudaFuncSetAttribute(attn_kernel, cudaFuncAttributeMaxDynamicSharedMemorySize, (int)smem);
        attn_kernel<<<dim3(SEQ / QT, NH), QT, smem>>>();
    }

    // 4) output projection: [4096,768] x [768,768]^T -> [4096,768]
    gemm_nt_kernel<<<dim3(DIM / 128, SEQ / 128), 256>>>(pao, wo, out, SEQ, DIM, DIM);
}

// round 2
// speedup vs baseline: 1.0333x; 1.0333x over previous
#include <cuda_runtime.h>
#include <cuda_bf16.h>

#define SEQ      4096
#define DIM      768
#define NH       12
#define HD       64
#define QKVDIM   2304
#define WIN      64      // WINDOW/2

// ---------------- scratch (device globals; no allocation allowed) -----------
__device__ float g_qkv[SEQ * QKVDIM];          // [s][e]
__device__ float g_q  [NH * SEQ * HD];         // [h][s][d]  (RoPE'd, pre-scaled)
__device__ float g_k  [NH * SEQ * HD];         // [h][s][d]  (RoPE'd)
__device__ float g_v  [NH * SEQ * HD];         // [h][s][d]
__device__ float g_ao [SEQ * DIM];             // [s][h*64+d]

// ------------- double-buffered SGEMM, C[m,n] = sum_k A[m,k]*B[n,k] ----------
// A: row-major [M,K], B: row-major [N,K]. BM in {64,128}, BN=128, BK=16.
// 256 threads; per-thread tile TMxS8 (TM = BM/16).
template<int BM>
__global__ void __launch_bounds__(256) gemm_db_kernel(
    const float* __restrict__ A, const float* __restrict__ B,
    float* __restrict__ C, int M, int N, int K)
{
    constexpr int TM = BM / 16;
    constexpr int NA = BM / 64;          // float4s of A per thread per chunk
    __shared__ float sA[2][16][BM + 4];
    __shared__ float sB[2][16][132];

    const int tid = threadIdx.x;
    const int m0 = blockIdx.y * BM;
    const int n0 = blockIdx.x * 128;
    const int tx = tid & 15;
    const int ty = tid >> 4;

    const float* Abase = A + (size_t)m0 * K;
    const float* Bbase = B + (size_t)n0 * K;

    float4 ra[NA], rb[2];

    auto gload = [&](int k0) {
#pragma unroll
        for (int i = 0; i < NA; i++) {
            int f = tid + i * 256;
            ra[i] = *(const float4*)(Abase + (size_t)(f >> 2) * K + k0 + (f & 3) * 4);
        }
#pragma unroll
        for (int i = 0; i < 2; i++) {
            int f = tid + i * 256;
            rb[i] = *(const float4*)(Bbase + (size_t)(f >> 2) * K + k0 + (f & 3) * 4);
        }
    };
    auto sstore = [&](int buf) {
#pragma unroll
        for (int i = 0; i < NA; i++) {
            int f = tid + i * 256;
            int r = f >> 2, k = (f & 3) * 4;
            sA[buf][k + 0][r] = ra[i].x; sA[buf][k + 1][r] = ra[i].y;
            sA[buf][k + 2][r] = ra[i].z; sA[buf][k + 3][r] = ra[i].w;
        }
#pragma unroll
        for (int i = 0; i < 2; i++) {
            int f = tid + i * 256;
            int r = f >> 2, k = (f & 3) * 4;
            sB[buf][k + 0][r] = rb[i].x; sB[buf][k + 1][r] = rb[i].y;
            sB[buf][k + 2][r] = rb[i].z; sB[buf][k + 3][r] = rb[i].w;
        }
    };

    float acc[TM][8] = {};

    auto compute = [&](int buf) {
#pragma unroll
        for (int kk = 0; kk < 16; kk++) {
            float arr[TM], brr[8];
            *(float4*)(arr) = *(const float4*)&sA[buf][kk][ty * TM];
            if constexpr (TM == 8)
                *(float4*)(arr + 4) = *(const float4*)&sA[buf][kk][ty * TM + 4];
            *(float4*)(brr)     = *(const float4*)&sB[buf][kk][tx * 8];
            *(float4*)(brr + 4) = *(const float4*)&sB[buf][kk][tx * 8 + 4];
#pragma unroll
            for (int i = 0; i < TM; i++)
#pragma unroll
                for (int j = 0; j < 8; j++)
                    acc[i][j] += arr[i] * brr[j];
        }
    };

    gload(0);
    sstore(0);
    __syncthreads();

    const int nch = K / 16;
    for (int ch = 1; ch < nch; ch++) {
        gload(ch * 16);              // prefetch next chunk (global -> regs)
        compute((ch - 1) & 1);       // compute current chunk from smem
        sstore(ch & 1);              // stage prefetched chunk into other buffer
        __syncthreads();
    }
    compute((nch - 1) & 1);

#pragma unroll
    for (int i = 0; i < TM; i++) {
        float* Crow = C + (size_t)(m0 + ty * TM + i) * N + n0 + tx * 8;
        *(float4*)(Crow)     = make_float4(acc[i][0], acc[i][1], acc[i][2], acc[i][3]);
        *(float4*)(Crow + 4) = make_float4(acc[i][4], acc[i][5], acc[i][6], acc[i][7]);
    }
}

// ---------------- split qkv + RoPE + transpose to [h][s][d] -----------------
__global__ void rope_split_kernel(const int* __restrict__ pos_ids)
{
    int idx = blockIdx.x * blockDim.x + threadIdx.x;   // over SEQ*NH*32
    if (idx >= SEQ * NH * 32) return;
    int i = idx & 31;
    int h = (idx >> 5) % NH;
    int s = idx / (32 * NH);

    float pos = (float)pos_ids[s];
    float inv = powf(10000.0f, -(float)i / 32.0f);
    float f = pos * inv;
    float c = cosf(f), sn = sinf(f);

    const float* row = g_qkv + (size_t)s * QKVDIM;
    int base = (h * SEQ + s) * HD;

    float q1 = row[h * HD + i], q2 = row[h * HD + i + 32];
    g_q[base + i]      = (q1 * c - q2 * sn) * 0.125f;   // fold 1/sqrt(64)
    g_q[base + i + 32] = (q2 * c + q1 * sn) * 0.125f;
    float k1 = row[DIM + h * HD + i], k2 = row[DIM + h * HD + i + 32];
    g_k[base + i]      = k1 * c - k2 * sn;
    g_k[base + i + 32] = k2 * c + k1 * sn;
    g_v[base + i]      = row[2 * DIM + h * HD + i];
    g_v[base + i + 32] = row[2 * DIM + h * HD + i + 32];
}

// ---------------- sliding-window attention ----------------------------------
#define QT   128
#define KT   256              // QT + 2*WIN
#define KPAD 68
__global__ void __launch_bounds__(128) attn_kernel()
{
    extern __shared__ float smem[];
    float* sK = smem;
    float* sV = smem + KT * KPAD;

    const int h    = blockIdx.y;
    const int tile = blockIdx.x;
    const int q    = tile * QT + threadIdx.x;
    const int kbase = tile * QT - WIN;

    const float* Kh = g_k + (size_t)h * SEQ * HD;
    const float* Vh = g_v + (size_t)h * SEQ * HD;

    for (int t = threadIdx.x; t < KT * (HD / 4); t += QT) {
        int r  = t >> 4;
        int c4 = t & 15;
        int gr = kbase + r;
        if (gr >= 0 && gr < SEQ) {
            *(float4*)(sK + r * KPAD + c4 * 4) = *(const float4*)(Kh + (size_t)gr * HD + c4 * 4);
            *(float4*)(sV + r * KPAD + c4 * 4) = *(const float4*)(Vh + (size_t)gr * HD + c4 * 4);
        }
    }
    __syncthreads();

    float qr[HD];
    const float* Qp = g_q + ((size_t)h * SEQ + q) * HD;
#pragma unroll
    for (int d = 0; d < HD; d++) qr[d] = Qp[d];

    float m = -1e30f, l = 0.f;
    float acc[HD];
#pragma unroll
    for (int d = 0; d < HD; d++) acc[d] = 0.f;

    const int lo = (q - WIN < 0) ? 0 : q - WIN;
    const int hi = (q + WIN > SEQ - 1) ? SEQ - 1 : q + WIN;

    for (int j = lo; j <= hi; j++) {
        const float* kr = sK + (j - kbase) * KPAD;
        float s = 0.f;
#pragma unroll
        for (int d4 = 0; d4 < HD / 4; d4++) {
            float4 kk = *(const float4*)(kr + 4 * d4);
            s += qr[4 * d4 + 0] * kk.x + qr[4 * d4 + 1] * kk.y
               + qr[4 * d4 + 2] * kk.z + qr[4 * d4 + 3] * kk.w;
        }
        if (s > m) {
            float corr = __expf(m - s);
            m = s;
            l *= corr;
#pragma unroll
            for (int d = 0; d < HD; d++) acc[d] *= corr;
        }
        float e = __expf(s - m);
        l += e;
        const float* vr = sV + (j - kbase) * KPAD;
#pragma unroll
        for (int d4 = 0; d4 < HD / 4; d4++) {
            float4 vv = *(const float4*)(vr + 4 * d4);
            acc[4 * d4 + 0] += e * vv.x;
            acc[4 * d4 + 1] += e * vv.y;
            acc[4 * d4 + 2] += e * vv.z;
            acc[4 * d4 + 3] += e * vv.w;
        }
    }

    float invl = 1.f / l;
    float* op = g_ao + (size_t)q * DIM + h * HD;
#pragma unroll
    for (int d4 = 0; d4 < HD / 4; d4++) {
        float4 o;
        o.x = acc[4 * d4 + 0] * invl;
        o.y = acc[4 * d4 + 1] * invl;
        o.z = acc[4 * d4 + 2] * invl;
        o.w = acc[4 * d4 + 3] * invl;
        *(float4*)(op + 4 * d4) = o;
    }
}

// ---------------- launch -----------------------------------------------------
extern "C" void kernel_launch(void* const* d_in, const int* in_sizes, int n_in,
                              void* d_out, int out_size)
{
    const float* x    = (const float*)d_in[0];
    const int*   pos  = (const int*)  d_in[1];
    const float* wqkv = (const float*)d_in[2];
    const float* wo   = (const float*)d_in[3];
    float*       out  = (float*)d_out;

    float *pqkv, *pao;
    cudaGetSymbolAddress((void**)&pqkv, g_qkv);
    cudaGetSymbolAddress((void**)&pao,  g_ao);

    // 1) QKV projection: [4096,768] x [2304,768]^T -> [4096,2304]
    gemm_db_kernel<128><<<dim3(QKVDIM / 128, SEQ / 128), 256>>>(x, wqkv, pqkv, SEQ, QKVDIM, DIM);

    // 2) split + RoPE + transpose
    {
        int total = SEQ * NH * 32;
        rope_split_kernel<<<(total + 255) / 256, 256>>>(pos);
    }

    // 3) sliding-window attention
    {
        size_t smem = (size_t)2 * KT * KPAD * sizeof(float);   // ~139 KB
        cudaFuncSetAttribute(attn_kernel, cudaFuncAttributeMaxDynamicSharedMemorySize, (int)smem);
        attn_kernel<<<dim3(SEQ / QT, NH), QT, smem>>>();
    }

    // 4) output projection: [4096,768] x [768,768]^T -> [4096,768]
    //    64-row tiles -> 384 blocks (tail fix: 2.6 waves instead of 1.3)
    gemm_db_kernel<64><<<dim3(DIM / 128, SEQ / 64), 256>>>(pao, wo, out, SEQ, DIM, DIM);
}

// round 4
// speedup vs baseline: 1.8340x; 1.7749x over previous
#include <cuda_runtime.h>
#include <cuda_bf16.h>
#include <cstdint>

#define SEQ      4096
#define DIM      768
#define NH       12
#define HD       64
#define QKVDIM   2304
#define WIN      64      // WINDOW/2

// ---------------- scratch (device globals; no allocation allowed) -----------
__device__ float g_qkv[SEQ * QKVDIM];          // [s][e]
__device__ float g_q  [NH * SEQ * HD];         // [h][s][d]  (RoPE'd, pre-scaled)
__device__ float g_k  [NH * SEQ * HD];         // [h][s][d]  (RoPE'd)
__device__ float g_v  [NH * SEQ * HD];         // [h][s][d]
__device__ float g_ao [SEQ * DIM];             // [s][h*64+d]

// =================== HMMA (mma.sync) GEMM, 3x bf16 compensation =============
// C[m,n] = sum_k A[m,k]*B[n,k]; A:[M,K] row-major, B:[N,K] row-major.
// M%128==0, N%128==0, K%32==0. 256 threads, CTA tile 128x128, BK=32.
// Each fp32 value x = hi + lo (both bf16); product uses hi*hi + hi*lo + lo*hi.

#define RS       40                 // smem row stride in bf16 (32 data + 8 pad)
#define TILE_E   (128 * RS)         // bf16 elems per matrix tile  (5120)
#define TILE_B   (TILE_E * 2)       // bytes per matrix tile       (10240)
#define BUF_B    (4 * TILE_B)       // Ahi,Alo,Bhi,Blo             (40960)
#define GEMM_SMEM (2 * BUF_B)       // double buffered             (81920)

__device__ __forceinline__ uint32_t smem_u32(const void* p) {
    uint32_t a;
    asm("{ .reg .u64 t; cvta.to.shared.u64 t, %1; cvt.u32.u64 %0, t; }" : "=r"(a) : "l"(p));
    return a;
}

#define LDSM4(r, addr) \
    asm volatile("ldmatrix.sync.aligned.m8n8.x4.shared.b16 {%0,%1,%2,%3}, [%4];" \
        : "=r"((r)[0]), "=r"((r)[1]), "=r"((r)[2]), "=r"((r)[3]) : "r"(addr))

#define MMA_BF16(d, a, b0, b1) \
    asm volatile("mma.sync.aligned.m16n8k16.row.col.f32.bf16.bf16.f32 " \
        "{%0,%1,%2,%3}, {%4,%5,%6,%7}, {%8,%9}, {%0,%1,%2,%3};" \
        : "+f"((d)[0]), "+f"((d)[1]), "+f"((d)[2]), "+f"((d)[3]) \
        : "r"((a)[0]), "r"((a)[1]), "r"((a)[2]), "r"((a)[3]), "r"(b0), "r"(b1))

__device__ __forceinline__ uint32_t pack_bf2(__nv_bfloat16 a, __nv_bfloat16 b) {
    __nv_bfloat162 t(a, b);
    return *reinterpret_cast<uint32_t*>(&t);
}
__device__ __forceinline__ void split2(float x, float y, uint32_t& hi, uint32_t& lo) {
    __nv_bfloat16 hx = __float2bfloat16(x);
    __nv_bfloat16 hy = __float2bfloat16(y);
    __nv_bfloat16 lx = __float2bfloat16(x - __bfloat162float(hx));
    __nv_bfloat16 ly = __float2bfloat16(y - __bfloat162float(hy));
    hi = pack_bf2(hx, hy);
    lo = pack_bf2(lx, ly);
}

__global__ void __launch_bounds__(256, 1) gemm_mma_kernel(
    const float* __restrict__ A, const float* __restrict__ B,
    float* __restrict__ C, int M, int N, int K)
{
    extern __shared__ char smem[];
    const uint32_t sb0 = smem_u32(smem);

    const int tid  = threadIdx.x;
    const int wid  = tid >> 5;
    const int lane = tid & 31;
    const int m0 = blockIdx.y * 128;
    const int n0 = blockIdx.x * 128;
    const int wm = (wid & 3) * 32;       // warp m-offset in tile
    const int wn = (wid >> 2) * 64;      // warp n-offset in tile

    const float* Ab = A + (size_t)m0 * K;
    const float* Bb = B + (size_t)n0 * K;

    float4 rA[4], rB[4];
    auto gload = [&](int kc) {
#pragma unroll
        for (int i = 0; i < 4; i++) {
            int f = tid + i * 256;
            int r = f >> 3, k4 = f & 7;
            rA[i] = *(const float4*)(Ab + (size_t)r * K + kc + k4 * 4);
            rB[i] = *(const float4*)(Bb + (size_t)r * K + kc + k4 * 4);
        }
    };
    auto sstore = [&](int buf) {
        char* s = smem + buf * BUF_B;
#pragma unroll
        for (int i = 0; i < 4; i++) {
            int f = tid + i * 256;
            int r = f >> 3, k4 = f & 7;
            uint32_t off = (uint32_t)(r * RS + k4 * 4) * 2;    // bytes
            uint2 hi, lo;
            split2(rA[i].x, rA[i].y, hi.x, lo.x);
            split2(rA[i].z, rA[i].w, hi.y, lo.y);
            *(uint2*)(s + off)          = hi;                  // A hi
            *(uint2*)(s + TILE_B + off) = lo;                  // A lo
            split2(rB[i].x, rB[i].y, hi.x, lo.x);
            split2(rB[i].z, rB[i].w, hi.y, lo.y);
            *(uint2*)(s + 2 * TILE_B + off) = hi;              // B hi
            *(uint2*)(s + 3 * TILE_B + off) = lo;              // B lo
        }
    };

    float acc[2][8][4];
#pragma unroll
    for (int i = 0; i < 2; i++)
#pragma unroll
        for (int j = 0; j < 8; j++)
#pragma unroll
            for (int t = 0; t < 4; t++) acc[i][j][t] = 0.f;

    auto compute = [&](int buf) {
        const uint32_t base = sb0 + buf * BUF_B;
        const uint32_t aHi = base, aLo = base + TILE_B;
        const uint32_t bHi = base + 2 * TILE_B, bLo = base + 3 * TILE_B;
#pragma unroll
        for (int ks = 0; ks < 2; ks++) {
            uint32_t Ah[2][4], Al[2][4];
#pragma unroll
            for (int mt = 0; mt < 2; mt++) {
                int r = wm + mt * 16 + (lane & 15);
                int c = ks * 16 + (lane >> 4) * 8;
                uint32_t off = (uint32_t)(r * RS + c) * 2;
                LDSM4(Ah[mt], aHi + off);
                LDSM4(Al[mt], aLo + off);
            }
#pragma unroll
            for (int p = 0; p < 4; p++) {
                int quad = lane >> 3, l8 = lane & 7;
                int n = wn + p * 16 + (quad >> 1) * 8 + l8;
                int c = ks * 16 + (quad & 1) * 8;
                uint32_t off = (uint32_t)(n * RS + c) * 2;
                uint32_t Bh[4], Bl[4];
                LDSM4(Bh, bHi + off);
                LDSM4(Bl, bLo + off);
#pragma unroll
                for (int sub = 0; sub < 2; sub++) {
#pragma unroll
                    for (int mt = 0; mt < 2; mt++) {
                        float* d = acc[mt][p * 2 + sub];
                        MMA_BF16(d, Ah[mt], Bh[2 * sub], Bh[2 * sub + 1]);
                        MMA_BF16(d, Ah[mt], Bl[2 * sub], Bl[2 * sub + 1]);
                        MMA_BF16(d, Al[mt], Bh[2 * sub], Bh[2 * sub + 1]);
                    }
                }
            }
        }
    };

    const int nch = K / 32;
    gload(0);
    sstore(0);
    __syncthreads();
    for (int c = 0; c < nch; c++) {
        if (c + 1 < nch) gload((c + 1) * 32);
        compute(c & 1);
        __syncthreads();
        if (c + 1 < nch) {
            sstore((c + 1) & 1);
            __syncthreads();
        }
    }

    // epilogue: m16n8 C-fragment layout
#pragma unroll
    for (int mt = 0; mt < 2; mt++) {
#pragma unroll
        for (int nt = 0; nt < 8; nt++) {
            int row = m0 + wm + mt * 16 + (lane >> 2);
            int col = n0 + wn + nt * 8 + (lane & 3) * 2;
            float* p0 = C + (size_t)row * N + col;
            float* p1 = C + (size_t)(row + 8) * N + col;
            *(float2*)p0 = make_float2(acc[mt][nt][0], acc[mt][nt][1]);
            *(float2*)p1 = make_float2(acc[mt][nt][2], acc[mt][nt][3]);
        }
    }
}

// ---------------- split qkv + RoPE + transpose to [h][s][d] -----------------
__global__ void rope_split_kernel(const int* __restrict__ pos_ids)
{
    int idx = blockIdx.x * blockDim.x + threadIdx.x;   // over SEQ*NH*32
    if (idx >= SEQ * NH * 32) return;
    int i = idx & 31;
    int h = (idx >> 5) % NH;
    int s = idx / (32 * NH);

    float pos = (float)pos_ids[s];
    float inv = powf(10000.0f, -(float)i / 32.0f);
    float f = pos * inv;
    float c = cosf(f), sn = sinf(f);

    const float* row = g_qkv + (size_t)s * QKVDIM;
    int base = (h * SEQ + s) * HD;

    float q1 = row[h * HD + i], q2 = row[h * HD + i + 32];
    g_q[base + i]      = (q1 * c - q2 * sn) * 0.125f;   // fold 1/sqrt(64)
    g_q[base + i + 32] = (q2 * c + q1 * sn) * 0.125f;
    float k1 = row[DIM + h * HD + i], k2 = row[DIM + h * HD + i + 32];
    g_k[base + i]      = k1 * c - k2 * sn;
    g_k[base + i + 32] = k2 * c + k1 * sn;
    g_v[base + i]      = row[2 * DIM + h * HD + i];
    g_v[base + i + 32] = row[2 * DIM + h * HD + i + 32];
}

// ---------------- sliding-window attention ----------------------------------
#define QT   128
#define KT   256              // QT + 2*WIN
#define KPAD 68
__global__ void __launch_bounds__(128) attn_kernel()
{
    extern __shared__ float asmem[];
    float* sK = asmem;
    float* sV = asmem + KT * KPAD;

    const int h    = blockIdx.y;
    const int tile = blockIdx.x;
    const int q    = tile * QT + threadIdx.x;
    const int kbase = tile * QT - WIN;

    const float* Kh = g_k + (size_t)h * SEQ * HD;
    const float* Vh = g_v + (size_t)h * SEQ * HD;

    for (int t = threadIdx.x; t < KT * (HD / 4); t += QT) {
        int r  = t >> 4;
        int c4 = t & 15;
        int gr = kbase + r;
        if (gr >= 0 && gr < SEQ) {
            *(float4*)(sK + r * KPAD + c4 * 4) = *(const float4*)(Kh + (size_t)gr * HD + c4 * 4);
            *(float4*)(sV + r * KPAD + c4 * 4) = *(const float4*)(Vh + (size_t)gr * HD + c4 * 4);
        }
    }
    __syncthreads();

    float qr[HD];
    const float* Qp = g_q + ((size_t)h * SEQ + q) * HD;
#pragma unroll
    for (int d = 0; d < HD; d++) qr[d] = Qp[d];

    float m = -1e30f, l = 0.f;
    float acc[HD];
#pragma unroll
    for (int d = 0; d < HD; d++) acc[d] = 0.f;

    const int lo = (q - WIN < 0) ? 0 : q - WIN;
    const int hi = (q + WIN > SEQ - 1) ? SEQ - 1 : q + WIN;

    for (int j = lo; j <= hi; j++) {
        const float* kr = sK + (j - kbase) * KPAD;
        float s = 0.f;
#pragma unroll
        for (int d4 = 0; d4 < HD / 4; d4++) {
            float4 kk = *(const float4*)(kr + 4 * d4);
            s += qr[4 * d4 + 0] * kk.x + qr[4 * d4 + 1] * kk.y
               + qr[4 * d4 + 2] * kk.z + qr[4 * d4 + 3] * kk.w;
        }
        if (s > m) {
            float corr = __expf(m - s);
            m = s;
            l *= corr;
#pragma unroll
            for (int d = 0; d < HD; d++) acc[d] *= corr;
        }
        float e = __expf(s - m);
        l += e;
        const float* vr = sV + (j - kbase) * KPAD;
#pragma unroll
        for (int d4 = 0; d4 < HD / 4; d4++) {
            float4 vv = *(const float4*)(vr + 4 * d4);
            acc[4 * d4 + 0] += e * vv.x;
            acc[4 * d4 + 1] += e * vv.y;
            acc[4 * d4 + 2] += e * vv.z;
            acc[4 * d4 + 3] += e * vv.w;
        }
    }

    float invl = 1.f / l;
    float* op = g_ao + (size_t)q * DIM + h * HD;
#pragma unroll
    for (int d4 = 0; d4 < HD / 4; d4++) {
        float4 o;
        o.x = acc[4 * d4 + 0] * invl;
        o.y = acc[4 * d4 + 1] * invl;
        o.z = acc[4 * d4 + 2] * invl;
        o.w = acc[4 * d4 + 3] * invl;
        *(float4*)(op + 4 * d4) = o;
    }
}

// ---------------- launch -----------------------------------------------------
extern "C" void kernel_launch(void* const* d_in, const int* in_sizes, int n_in,
                              void* d_out, int out_size)
{
    const float* x    = (const float*)d_in[0];
    const int*   pos  = (const int*)  d_in[1];
    const float* wqkv = (const float*)d_in[2];
    const float* wo   = (const float*)d_in[3];
    float*       out  = (float*)d_out;

    float *pqkv, *pao;
    cudaGetSymbolAddress((void**)&pqkv, g_qkv);
    cudaGetSymbolAddress((void**)&pao,  g_ao);

    cudaFuncSetAttribute(gemm_mma_kernel, cudaFuncAttributeMaxDynamicSharedMemorySize, GEMM_SMEM);
    cudaFuncSetAttribute(attn_kernel, cudaFuncAttributeMaxDynamicSharedMemorySize,
                         (int)(2 * KT * KPAD * sizeof(float)));

    // 1) QKV projection: [4096,768] x [2304,768]^T -> [4096,2304]
    gemm_mma_kernel<<<dim3(QKVDIM / 128, SEQ / 128), 256, GEMM_SMEM>>>(x, wqkv, pqkv, SEQ, QKVDIM, DIM);

    // 2) split + RoPE + transpose
    {
        int total = SEQ * NH * 32;
        rope_split_kernel<<<(total + 255) / 256, 256>>>(pos);
    }

    // 3) sliding-window attention
    {
        size_t smem = (size_t)2 * KT * KPAD * sizeof(float);   // ~139 KB
        attn_kernel<<<dim3(SEQ / QT, NH), QT, smem>>>();
    }

    // 4) output projection: [4096,768] x [768,768]^T -> [4096,768]
    gemm_mma_kernel<<<dim3(DIM / 128, SEQ / 128), 256, GEMM_SMEM>>>(pao, wo, out, SEQ, DIM, DIM);
}

// round 5
// speedup vs baseline: 2.6243x; 1.4309x over previous
#include <cuda_runtime.h>
#include <cuda_bf16.h>
#include <cstdint>

#define SEQ      4096
#define DIM      768
#define NH       12
#define HD       64
#define QKVDIM   2304
#define WIN      64      // WINDOW/2

// ---------------- scratch (device globals; no allocation allowed) -----------
__device__ float g_qkv[SEQ * QKVDIM];          // [s][e]
__device__ float g_q  [NH * SEQ * HD];         // [h][s][d]  (RoPE'd, pre-scaled)
__device__ float g_k  [NH * SEQ * HD];         // [h][s][d]  (RoPE'd)
__device__ float g_v  [NH * SEQ * HD];         // [h][s][d]
__device__ float g_ao [SEQ * DIM];             // [s][h*64+d]

// =================== common MMA helpers ======================================
__device__ __forceinline__ uint32_t smem_u32(const void* p) {
    uint32_t a;
    asm("{ .reg .u64 t; cvta.to.shared.u64 t, %1; cvt.u32.u64 %0, t; }" : "=r"(a) : "l"(p));
    return a;
}
#define LDSM4(r, addr) \
    asm volatile("ldmatrix.sync.aligned.m8n8.x4.shared.b16 {%0,%1,%2,%3}, [%4];" \
        : "=r"((r)[0]), "=r"((r)[1]), "=r"((r)[2]), "=r"((r)[3]) : "r"(addr))
#define LDSM4T(r, addr) \
    asm volatile("ldmatrix.sync.aligned.m8n8.x4.trans.shared.b16 {%0,%1,%2,%3}, [%4];" \
        : "=r"((r)[0]), "=r"((r)[1]), "=r"((r)[2]), "=r"((r)[3]) : "r"(addr))
#define MMA_BF16(d, a, b0, b1) \
    asm volatile("mma.sync.aligned.m16n8k16.row.col.f32.bf16.bf16.f32 " \
        "{%0,%1,%2,%3}, {%4,%5,%6,%7}, {%8,%9}, {%0,%1,%2,%3};" \
        : "+f"((d)[0]), "+f"((d)[1]), "+f"((d)[2]), "+f"((d)[3]) \
        : "r"((a)[0]), "r"((a)[1]), "r"((a)[2]), "r"((a)[3]), "r"(b0), "r"(b1))

__device__ __forceinline__ uint32_t pack_bf2(__nv_bfloat16 a, __nv_bfloat16 b) {
    __nv_bfloat162 t(a, b);
    return *reinterpret_cast<uint32_t*>(&t);
}
__device__ __forceinline__ void split2(float x, float y, uint32_t& hi, uint32_t& lo) {
    __nv_bfloat16 hx = __float2bfloat16(x);
    __nv_bfloat16 hy = __float2bfloat16(y);
    __nv_bfloat16 lx = __float2bfloat16(x - __bfloat162float(hx));
    __nv_bfloat16 ly = __float2bfloat16(y - __bfloat162float(hy));
    hi = pack_bf2(hx, hy);
    lo = pack_bf2(lx, ly);
}

// =================== HMMA GEMM, 3x bf16 compensation =========================
#define RS       40
#define TILE_E   (128 * RS)
#define TILE_B   (TILE_E * 2)
#define BUF_B    (4 * TILE_B)
#define GEMM_SMEM (2 * BUF_B)

__global__ void __launch_bounds__(256, 1) gemm_mma_kernel(
    const float* __restrict__ A, const float* __restrict__ B,
    float* __restrict__ C, int M, int N, int K)
{
    extern __shared__ char smem[];
    const uint32_t sb0 = smem_u32(smem);

    const int tid  = threadIdx.x;
    const int wid  = tid >> 5;
    const int lane = tid & 31;
    const int m0 = blockIdx.y * 128;
    const int n0 = blockIdx.x * 128;
    const int wm = (wid & 3) * 32;
    const int wn = (wid >> 2) * 64;

    const float* Ab = A + (size_t)m0 * K;
    const float* Bb = B + (size_t)n0 * K;

    float4 rA[4], rB[4];
    auto gload = [&](int kc) {
#pragma unroll
        for (int i = 0; i < 4; i++) {
            int f = tid + i * 256;
            int r = f >> 3, k4 = f & 7;
            rA[i] = *(const float4*)(Ab + (size_t)r * K + kc + k4 * 4);
            rB[i] = *(const float4*)(Bb + (size_t)r * K + kc + k4 * 4);
        }
    };
    auto sstore = [&](int buf) {
        char* s = smem + buf * BUF_B;
#pragma unroll
        for (int i = 0; i < 4; i++) {
            int f = tid + i * 256;
            int r = f >> 3, k4 = f & 7;
            uint32_t off = (uint32_t)(r * RS + k4 * 4) * 2;
            uint2 hi, lo;
            split2(rA[i].x, rA[i].y, hi.x, lo.x);
            split2(rA[i].z, rA[i].w, hi.y, lo.y);
            *(uint2*)(s + off)          = hi;
            *(uint2*)(s + TILE_B + off) = lo;
            split2(rB[i].x, rB[i].y, hi.x, lo.x);
            split2(rB[i].z, rB[i].w, hi.y, lo.y);
            *(uint2*)(s + 2 * TILE_B + off) = hi;
            *(uint2*)(s + 3 * TILE_B + off) = lo;
        }
    };

    float acc[2][8][4];
#pragma unroll
    for (int i = 0; i < 2; i++)
#pragma unroll
        for (int j = 0; j < 8; j++)
#pragma unroll
            for (int t = 0; t < 4; t++) acc[i][j][t] = 0.f;

    auto compute = [&](int buf) {
        const uint32_t base = sb0 + buf * BUF_B;
        const uint32_t aHi = base, aLo = base + TILE_B;
        const uint32_t bHi = base + 2 * TILE_B, bLo = base + 3 * TILE_B;
#pragma unroll
        for (int ks = 0; ks < 2; ks++) {
            uint32_t Ah[2][4], Al[2][4];
#pragma unroll
            for (int mt = 0; mt < 2; mt++) {
                int r = wm + mt * 16 + (lane & 15);
                int c = ks * 16 + (lane >> 4) * 8;
                uint32_t off = (uint32_t)(r * RS + c) * 2;
                LDSM4(Ah[mt], aHi + off);
                LDSM4(Al[mt], aLo + off);
            }
#pragma unroll
            for (int p = 0; p < 4; p++) {
                int quad = lane >> 3, l8 = lane & 7;
                int n = wn + p * 16 + (quad >> 1) * 8 + l8;
                int c = ks * 16 + (quad & 1) * 8;
                uint32_t off = (uint32_t)(n * RS + c) * 2;
                uint32_t Bh[4], Bl[4];
                LDSM4(Bh, bHi + off);
                LDSM4(Bl, bLo + off);
#pragma unroll
                for (int sub = 0; sub < 2; sub++) {
#pragma unroll
                    for (int mt = 0; mt < 2; mt++) {
                        float* d = acc[mt][p * 2 + sub];
                        MMA_BF16(d, Ah[mt], Bh[2 * sub], Bh[2 * sub + 1]);
                        MMA_BF16(d, Ah[mt], Bl[2 * sub], Bl[2 * sub + 1]);
                        MMA_BF16(d, Al[mt], Bh[2 * sub], Bh[2 * sub + 1]);
                    }
                }
            }
        }
    };

    const int nch = K / 32;
    gload(0);
    sstore(0);
    __syncthreads();
    for (int c = 0; c < nch; c++) {
        if (c + 1 < nch) gload((c + 1) * 32);
        compute(c & 1);
        __syncthreads();
        if (c + 1 < nch) {
            sstore((c + 1) & 1);
            __syncthreads();
        }
    }

#pragma unroll
    for (int mt = 0; mt < 2; mt++) {
#pragma unroll
        for (int nt = 0; nt < 8; nt++) {
            int row = m0 + wm + mt * 16 + (lane >> 2);
            int col = n0 + wn + nt * 8 + (lane & 3) * 2;
            float* p0 = C + (size_t)row * N + col;
            float* p1 = C + (size_t)(row + 8) * N + col;
            *(float2*)p0 = make_float2(acc[mt][nt][0], acc[mt][nt][1]);
            *(float2*)p1 = make_float2(acc[mt][nt][2], acc[mt][nt][3]);
        }
    }
}

// ---------------- split qkv + RoPE + transpose to [h][s][d] -----------------
__global__ void rope_split_kernel(const int* __restrict__ pos_ids)
{
    int idx = blockIdx.x * blockDim.x + threadIdx.x;
    if (idx >= SEQ * NH * 32) return;
    int i = idx & 31;
    int h = (idx >> 5) % NH;
    int s = idx / (32 * NH);

    float pos = (float)pos_ids[s];
    float inv = powf(10000.0f, -(float)i / 32.0f);
    float f = pos * inv;
    float c = cosf(f), sn = sinf(f);

    const float* row = g_qkv + (size_t)s * QKVDIM;
    int base = (h * SEQ + s) * HD;

    float q1 = row[h * HD + i], q2 = row[h * HD + i + 32];
    g_q[base + i]      = (q1 * c - q2 * sn) * 0.125f;
    g_q[base + i + 32] = (q2 * c + q1 * sn) * 0.125f;
    float k1 = row[DIM + h * HD + i], k2 = row[DIM + h * HD + i + 32];
    g_k[base + i]      = k1 * c - k2 * sn;
    g_k[base + i + 32] = k2 * c + k1 * sn;
    g_v[base + i]      = row[2 * DIM + h * HD + i];
    g_v[base + i + 32] = row[2 * DIM + h * HD + i + 32];
}

// ============== tensor-core sliding-window attention =========================
// block = (q-tile 128, head). 8 warps; warp w owns q rows [w*16, w*16+16).
// Keys staged: KT=256 (tile*128-64 .. +191). 2 chunks of 128 keys, online softmax.
// Q,K,V split bf16 hi/lo in smem (pitch 72 bf16). Full 3-MMA compensation.
#define APITCH 72
#define A_QH 0
#define A_QL (128 * APITCH)          // 9216
#define A_KH (2 * 128 * APITCH)      // 18432
#define A_KL (A_KH + 256 * APITCH)
#define A_VH (A_KH + 2 * 256 * APITCH)
#define A_VL (A_VH + 256 * APITCH)
#define ATTN_SMEM ((A_VL + 256 * APITCH) * 2)   // bytes = 184320

__global__ void __launch_bounds__(256, 1) attn_mma_kernel()
{
    extern __shared__ __align__(16) char asm_[];
    __nv_bfloat16* sb = (__nv_bfloat16*)asm_;
    const uint32_t sbase = smem_u32(asm_);

    const int tid = threadIdx.x;
    const int w = tid >> 5;
    const int lane = tid & 31;
    const int h = blockIdx.y;
    const int tile = blockIdx.x;
    const int kbase = tile * 128 - WIN;

    const float* Qg = g_q + ((size_t)h * SEQ + tile * 128) * HD;
    const float* Kg = g_k + (size_t)h * SEQ * HD;
    const float* Vg = g_v + (size_t)h * SEQ * HD;

    // ---- stage Q (128 x 64) ----
#pragma unroll
    for (int i = 0; i < 8; i++) {
        int f = tid + i * 256;
        int r = f >> 4, c4 = f & 15;
        float4 v = *(const float4*)(Qg + (size_t)r * HD + c4 * 4);
        uint2 hi, lo;
        split2(v.x, v.y, hi.x, lo.x);
        split2(v.z, v.w, hi.y, lo.y);
        int off = r * APITCH + c4 * 4;
        *(uint2*)(sb + A_QH + off) = hi;
        *(uint2*)(sb + A_QL + off) = lo;
    }
    // ---- stage K and V (256 x 64 each), zero-fill OOB keys ----
#pragma unroll
    for (int i = 0; i < 16; i++) {
        int f = tid + i * 256;
        int r = f >> 4, c4 = f & 15;
        int key = kbase + r;
        bool ok = (key >= 0) && (key < SEQ);
        float4 kv = make_float4(0.f, 0.f, 0.f, 0.f);
        float4 vv = make_float4(0.f, 0.f, 0.f, 0.f);
        if (ok) {
            kv = *(const float4*)(Kg + (size_t)key * HD + c4 * 4);
            vv = *(const float4*)(Vg + (size_t)key * HD + c4 * 4);
        }
        uint2 hi, lo;
        int off = r * APITCH + c4 * 4;
        split2(kv.x, kv.y, hi.x, lo.x);
        split2(kv.z, kv.w, hi.y, lo.y);
        *(uint2*)(sb + A_KH + off) = hi;
        *(uint2*)(sb + A_KL + off) = lo;
        split2(vv.x, vv.y, hi.x, lo.x);
        split2(vv.z, vv.w, hi.y, lo.y);
        *(uint2*)(sb + A_VH + off) = hi;
        *(uint2*)(sb + A_VL + off) = lo;
    }
    __syncthreads();

    float m0 = -1e30f, m1 = -1e30f, l0 = 0.f, l1 = 0.f;
    float O[8][4];
#pragma unroll
    for (int j = 0; j < 8; j++)
#pragma unroll
        for (int t = 0; t < 4; t++) O[j][t] = 0.f;

    const int q0 = tile * 128 + w * 16 + (lane >> 2);

    for (int c = 0; c < 2; c++) {
        // active 16-key groups for this warp/chunk
        int lo_col = w * 16 - 128 * c;
        int hi_col = lo_col + 143;
        int t_lo = lo_col < 0 ? 0 : (lo_col >> 4);
        int t_hi = (hi_col >> 4) < 7 ? (hi_col >> 4) : 7;

        float S[16][4];
#pragma unroll
        for (int b = 0; b < 16; b++)
#pragma unroll
            for (int t = 0; t < 4; t++) S[b][t] = 0.f;

        // ---- S = Q K^T over active groups ----
#pragma unroll
        for (int ks = 0; ks < 4; ks++) {
            uint32_t Ah[4], Al[4];
            uint32_t aoff = (uint32_t)((w * 16 + (lane & 15)) * APITCH + ks * 16 + (lane >> 4) * 8) * 2;
            LDSM4(Ah, sbase + A_QH * 2 + aoff);
            LDSM4(Al, sbase + A_QL * 2 + aoff);
#pragma unroll
            for (int g = 0; g < 8; g++) {
                if (g < t_lo || g > t_hi) continue;
                int quad = lane >> 3, l8 = lane & 7;
                int n = c * 128 + g * 16 + ((quad >> 1) & 1) * 8 + l8;
                int cc = ks * 16 + (quad & 1) * 8;
                uint32_t boff = (uint32_t)(n * APITCH + cc) * 2;
                uint32_t Bh[4], Bl[4];
                LDSM4(Bh, sbase + A_KH * 2 + boff);
                LDSM4(Bl, sbase + A_KL * 2 + boff);
#pragma unroll
                for (int sub = 0; sub < 2; sub++) {
                    float* d = S[g * 2 + sub];
                    MMA_BF16(d, Ah, Bh[2 * sub], Bh[2 * sub + 1]);
                    MMA_BF16(d, Ah, Bl[2 * sub], Bl[2 * sub + 1]);
                    MMA_BF16(d, Al, Bh[2 * sub], Bh[2 * sub + 1]);
                }
            }
        }

        // ---- mask + row max ----
        float mc0 = -1e30f, mc1 = -1e30f;
#pragma unroll
        for (int b = 0; b < 16; b++) {
            if ((b >> 1) < t_lo || (b >> 1) > t_hi) continue;
            int k0g = kbase + c * 128 + b * 8 + (lane & 3) * 2;
#pragma unroll
            for (int t = 0; t < 4; t++) {
                int kg = k0g + (t & 1);
                int qq = q0 + (t >> 1) * 8;
                bool ok = (kg >= 0) && (kg < SEQ) && (kg >= qq - WIN) && (kg <= qq + WIN);
                if (!ok) S[b][t] = -1e30f;
            }
            mc0 = fmaxf(mc0, fmaxf(S[b][0], S[b][1]));
            mc1 = fmaxf(mc1, fmaxf(S[b][2], S[b][3]));
        }
        mc0 = fmaxf(mc0, __shfl_xor_sync(0xffffffffu, mc0, 1));
        mc0 = fmaxf(mc0, __shfl_xor_sync(0xffffffffu, mc0, 2));
        mc1 = fmaxf(mc1, __shfl_xor_sync(0xffffffffu, mc1, 1));
        mc1 = fmaxf(mc1, __shfl_xor_sync(0xffffffffu, mc1, 2));

        float nm0 = fmaxf(m0, mc0), nm1 = fmaxf(m1, mc1);
        float f0 = __expf(m0 - nm0), f1 = __expf(m1 - nm1);
        l0 *= f0; l1 *= f1;
#pragma unroll
        for (int j = 0; j < 8; j++) {
            O[j][0] *= f0; O[j][1] *= f0;
            O[j][2] *= f1; O[j][3] *= f1;
        }
        m0 = nm0; m1 = nm1;

        // ---- P = exp(S - m), split to bf16 hi/lo A-fragments ----
        uint32_t Ph[16][2], Pl[16][2];
        float s0 = 0.f, s1 = 0.f;
#pragma unroll
        for (int b = 0; b < 16; b++) {
            if ((b >> 1) < t_lo || (b >> 1) > t_hi) continue;
            float p0 = __expf(S[b][0] - m0), p1 = __expf(S[b][1] - m0);
            float p2 = __expf(S[b][2] - m1), p3 = __expf(S[b][3] - m1);
            s0 += p0 + p1; s1 += p2 + p3;
            split2(p0, p1, Ph[b][0], Pl[b][0]);
            split2(p2, p3, Ph[b][1], Pl[b][1]);
        }
        s0 += __shfl_xor_sync(0xffffffffu, s0, 1);
        s0 += __shfl_xor_sync(0xffffffffu, s0, 2);
        s1 += __shfl_xor_sync(0xffffffffu, s1, 1);
        s1 += __shfl_xor_sync(0xffffffffu, s1, 2);
        l0 += s0; l1 += s1;

        // ---- O += P V over active k16 groups ----
#pragma unroll
        for (int kk = 0; kk < 8; kk++) {
            if (kk < t_lo || kk > t_hi) continue;
            uint32_t Aph[4] = {Ph[2 * kk][0], Ph[2 * kk][1], Ph[2 * kk + 1][0], Ph[2 * kk + 1][1]};
            uint32_t Apl[4] = {Pl[2 * kk][0], Pl[2 * kk][1], Pl[2 * kk + 1][0], Pl[2 * kk + 1][1]};
            int krow = c * 128 + kk * 16 + (lane & 7) + ((lane >> 3) & 1) * 8;
#pragma unroll
            for (int g = 0; g < 4; g++) {
                uint32_t voff = (uint32_t)(krow * APITCH + g * 16 + (lane >> 4) * 8) * 2;
                uint32_t Bh[4], Bl[4];
                LDSM4T(Bh, sbase + A_VH * 2 + voff);
                LDSM4T(Bl, sbase + A_VL * 2 + voff);
#pragma unroll
                for (int sub = 0; sub < 2; sub++) {
                    float* d = O[g * 2 + sub];
                    MMA_BF16(d, Aph, Bh[2 * sub], Bh[2 * sub + 1]);
                    MMA_BF16(d, Aph, Bl[2 * sub], Bl[2 * sub + 1]);
                    MMA_BF16(d, Apl, Bh[2 * sub], Bh[2 * sub + 1]);
                }
            }
        }
    }

    // ---- write normalized output ----
    float i0 = 1.f / l0, i1 = 1.f / l1;
    float* o0 = g_ao + (size_t)q0 * DIM + h * HD;
    float* o1 = g_ao + (size_t)(q0 + 8) * DIM + h * HD;
#pragma unroll
    for (int j = 0; j < 8; j++) {
        int col = j * 8 + (lane & 3) * 2;
        *(float2*)(o0 + col) = make_float2(O[j][0] * i0, O[j][1] * i0);
        *(float2*)(o1 + col) = make_float2(O[j][2] * i1, O[j][3] * i1);
    }
}

// ---------------- launch -----------------------------------------------------
extern "C" void kernel_launch(void* const* d_in, const int* in_sizes, int n_in,
                              void* d_out, int out_size)
{
    const float* x    = (const float*)d_in[0];
    const int*   pos  = (const int*)  d_in[1];
    const float* wqkv = (const float*)d_in[2];
    const float* wo   = (const float*)d_in[3];
    float*       out  = (float*)d_out;

    float *pqkv, *pao;
    cudaGetSymbolAddress((void**)&pqkv, g_qkv);
    cudaGetSymbolAddress((void**)&pao,  g_ao);

    cudaFuncSetAttribute(gemm_mma_kernel, cudaFuncAttributeMaxDynamicSharedMemorySize, GEMM_SMEM);
    cudaFuncSetAttribute(attn_mma_kernel, cudaFuncAttributeMaxDynamicSharedMemorySize, ATTN_SMEM);

    // 1) QKV projection: [4096,768] x [2304,768]^T -> [4096,2304]
    gemm_mma_kernel<<<dim3(QKVDIM / 128, SEQ / 128), 256, GEMM_SMEM>>>(x, wqkv, pqkv, SEQ, QKVDIM, DIM);

    // 2) split + RoPE + transpose
    {
        int total = SEQ * NH * 32;
        rope_split_kernel<<<(total + 255) / 256, 256>>>(pos);
    }

    // 3) sliding-window attention (tensor cores)
    attn_mma_kernel<<<dim3(SEQ / 128, NH), 256, ATTN_SMEM>>>();

    // 4) output projection: [4096,768] x [768,768]^T -> [4096,768]
    gemm_mma_kernel<<<dim3(DIM / 128, SEQ / 128), 256, GEMM_SMEM>>>(pao, wo, out, SEQ, DIM, DIM);
}

// round 6
// speedup vs baseline: 2.8084x; 1.0702x over previous
#include <cuda_runtime.h>
#include <cuda_bf16.h>
#include <cstdint>

#define SEQ      4096
#define DIM      768
#define NH       12
#define HD       64
#define QKVDIM   2304
#define WIN      64      // WINDOW/2

// ---------------- scratch (device globals; no allocation allowed) -----------
__device__ float g_qkv[SEQ * QKVDIM];          // [s][e]
__device__ float g_q  [NH * SEQ * HD];         // [h][s][d]  (RoPE'd, pre-scaled)
__device__ float g_k  [NH * SEQ * HD];         // [h][s][d]  (RoPE'd)
__device__ float g_v  [NH * SEQ * HD];         // [h][s][d]
__device__ float g_ao [SEQ * DIM];             // [s][h*64+d]

// =================== common MMA helpers ======================================
__device__ __forceinline__ uint32_t smem_u32(const void* p) {
    uint32_t a;
    asm("{ .reg .u64 t; cvta.to.shared.u64 t, %1; cvt.u32.u64 %0, t; }" : "=r"(a) : "l"(p));
    return a;
}
#define LDSM4(r, addr) \
    asm volatile("ldmatrix.sync.aligned.m8n8.x4.shared.b16 {%0,%1,%2,%3}, [%4];" \
        : "=r"((r)[0]), "=r"((r)[1]), "=r"((r)[2]), "=r"((r)[3]) : "r"(addr))
#define LDSM4T(r, addr) \
    asm volatile("ldmatrix.sync.aligned.m8n8.x4.trans.shared.b16 {%0,%1,%2,%3}, [%4];" \
        : "=r"((r)[0]), "=r"((r)[1]), "=r"((r)[2]), "=r"((r)[3]) : "r"(addr))
#define MMA_BF16(d, a, b0, b1) \
    asm volatile("mma.sync.aligned.m16n8k16.row.col.f32.bf16.bf16.f32 " \
        "{%0,%1,%2,%3}, {%4,%5,%6,%7}, {%8,%9}, {%0,%1,%2,%3};" \
        : "+f"((d)[0]), "+f"((d)[1]), "+f"((d)[2]), "+f"((d)[3]) \
        : "r"((a)[0]), "r"((a)[1]), "r"((a)[2]), "r"((a)[3]), "r"(b0), "r"(b1))

__device__ __forceinline__ uint32_t pack_bf2(__nv_bfloat16 a, __nv_bfloat16 b) {
    __nv_bfloat162 t(a, b);
    return *reinterpret_cast<uint32_t*>(&t);
}
__device__ __forceinline__ void split2(float x, float y, uint32_t& hi, uint32_t& lo) {
    __nv_bfloat16 hx = __float2bfloat16(x);
    __nv_bfloat16 hy = __float2bfloat16(y);
    __nv_bfloat16 lx = __float2bfloat16(x - __bfloat162float(hx));
    __nv_bfloat16 ly = __float2bfloat16(y - __bfloat162float(hy));
    hi = pack_bf2(hx, hy);
    lo = pack_bf2(lx, ly);
}

// =================== HMMA GEMM, 3x bf16 compensation =========================
// C[m,n] = sum_k A[m,k]*B[n,k]; A:[M,K] rm, B:[N,K] rm. BK=32, 256 threads.
// BM=128: warp tile 32x64 (4x2 warps). BM=64: warp tile 32x32 (2x4 warps).
#define RS 40                               // smem row stride in bf16

template<int BM>
__global__ void __launch_bounds__(256, 1) gemm_mma_kernel(
    const float* __restrict__ A, const float* __restrict__ B,
    float* __restrict__ C, int M, int N, int K)
{
    constexpr int NT  = (BM == 128) ? 8 : 4;     // n-subtiles of 8 cols per warp
    constexpr int NA  = BM / 32;                 // A float4 loads per thread
    constexpr int TA  = BM * RS * 2;             // A tile bytes
    constexpr int TB  = 128 * RS * 2;            // B tile bytes
    constexpr int BUF = 2 * TA + 2 * TB;         // Ahi,Alo,Bhi,Blo

    extern __shared__ char smem[];
    const uint32_t sb0 = smem_u32(smem);

    const int tid  = threadIdx.x;
    const int wid  = tid >> 5;
    const int lane = tid & 31;
    const int m0 = blockIdx.y * BM;
    const int n0 = blockIdx.x * 128;
    const int wm = (BM == 128) ? (wid & 3) * 32 : (wid & 1) * 32;
    const int wn = (BM == 128) ? (wid >> 2) * 64 : (wid >> 1) * 32;

    const float* Ab = A + (size_t)m0 * K;
    const float* Bb = B + (size_t)n0 * K;

    float4 rA[NA], rB[4];
    auto gload = [&](int kc) {
#pragma unroll
        for (int i = 0; i < NA; i++) {
            int f = tid + i * 256;
            int r = f >> 3, k4 = f & 7;
            rA[i] = *(const float4*)(Ab + (size_t)r * K + kc + k4 * 4);
        }
#pragma unroll
        for (int i = 0; i < 4; i++) {
            int f = tid + i * 256;
            int r = f >> 3, k4 = f & 7;
            rB[i] = *(const float4*)(Bb + (size_t)r * K + kc + k4 * 4);
        }
    };
    auto sstore = [&](int buf) {
        char* s = smem + buf * BUF;
#pragma unroll
        for (int i = 0; i < NA; i++) {
            int f = tid + i * 256;
            int r = f >> 3, k4 = f & 7;
            uint32_t off = (uint32_t)(r * RS + k4 * 4) * 2;
            uint2 hi, lo;
            split2(rA[i].x, rA[i].y, hi.x, lo.x);
            split2(rA[i].z, rA[i].w, hi.y, lo.y);
            *(uint2*)(s + off)      = hi;
            *(uint2*)(s + TA + off) = lo;
        }
#pragma unroll
        for (int i = 0; i < 4; i++) {
            int f = tid + i * 256;
            int r = f >> 3, k4 = f & 7;
            uint32_t off = (uint32_t)(r * RS + k4 * 4) * 2;
            uint2 hi, lo;
            split2(rB[i].x, rB[i].y, hi.x, lo.x);
            split2(rB[i].z, rB[i].w, hi.y, lo.y);
            *(uint2*)(s + 2 * TA + off)      = hi;
            *(uint2*)(s + 2 * TA + TB + off) = lo;
        }
    };

    float acc[2][NT][4];
#pragma unroll
    for (int i = 0; i < 2; i++)
#pragma unroll
        for (int j = 0; j < NT; j++)
#pragma unroll
            for (int t = 0; t < 4; t++) acc[i][j][t] = 0.f;

    auto compute = [&](int buf) {
        const uint32_t base = sb0 + buf * BUF;
        const uint32_t aHi = base, aLo = base + TA;
        const uint32_t bHi = base + 2 * TA, bLo = base + 2 * TA + TB;
#pragma unroll
        for (int ks = 0; ks < 2; ks++) {
            uint32_t Ah[2][4], Al[2][4];
#pragma unroll
            for (int mt = 0; mt < 2; mt++) {
                int r = wm + mt * 16 + (lane & 15);
                int c = ks * 16 + (lane >> 4) * 8;
                uint32_t off = (uint32_t)(r * RS + c) * 2;
                LDSM4(Ah[mt], aHi + off);
                LDSM4(Al[mt], aLo + off);
            }
#pragma unroll
            for (int p = 0; p < NT / 2; p++) {
                int quad = lane >> 3, l8 = lane & 7;
                int n = wn + p * 16 + (quad >> 1) * 8 + l8;
                int c = ks * 16 + (quad & 1) * 8;
                uint32_t off = (uint32_t)(n * RS + c) * 2;
                uint32_t Bh[4], Bl[4];
                LDSM4(Bh, bHi + off);
                LDSM4(Bl, bLo + off);
#pragma unroll
                for (int sub = 0; sub < 2; sub++) {
#pragma unroll
                    for (int mt = 0; mt < 2; mt++) {
                        float* d = acc[mt][p * 2 + sub];
                        MMA_BF16(d, Ah[mt], Bh[2 * sub], Bh[2 * sub + 1]);
                        MMA_BF16(d, Ah[mt], Bl[2 * sub], Bl[2 * sub + 1]);
                        MMA_BF16(d, Al[mt], Bh[2 * sub], Bh[2 * sub + 1]);
                    }
                }
            }
        }
    };

    const int nch = K / 32;
    gload(0);
    sstore(0);
    __syncthreads();
    // single barrier per chunk: sstore targets the buffer last READ two
    // iterations ago; the barrier at the end of the previous iteration
    // already ordered those reads before this write.
    for (int c = 0; c < nch; c++) {
        if (c + 1 < nch) gload((c + 1) * 32);
        compute(c & 1);
        if (c + 1 < nch) {
            sstore((c + 1) & 1);
            __syncthreads();
        }
    }

#pragma unroll
    for (int mt = 0; mt < 2; mt++) {
#pragma unroll
        for (int nt = 0; nt < NT; nt++) {
            int row = m0 + wm + mt * 16 + (lane >> 2);
            int col = n0 + wn + nt * 8 + (lane & 3) * 2;
            float* p0 = C + (size_t)row * N + col;
            float* p1 = C + (size_t)(row + 8) * N + col;
            *(float2*)p0 = make_float2(acc[mt][nt][0], acc[mt][nt][1]);
            *(float2*)p1 = make_float2(acc[mt][nt][2], acc[mt][nt][3]);
        }
    }
}
#define GEMM_SMEM_128 (2 * (2 * 128 * RS * 2 + 2 * 128 * RS * 2))   // 81920
#define GEMM_SMEM_64  (2 * (2 * 64 * RS * 2 + 2 * 128 * RS * 2))    // 61440

// ---------------- split qkv + RoPE + transpose to [h][s][d] -----------------
__global__ void rope_split_kernel(const int* __restrict__ pos_ids)
{
    int idx = blockIdx.x * blockDim.x + threadIdx.x;
    if (idx >= SEQ * NH * 32) return;
    int i = idx & 31;
    int h = (idx >> 5) % NH;
    int s = idx / (32 * NH);

    float pos = (float)pos_ids[s];
    float inv = powf(10000.0f, -(float)i / 32.0f);
    float f = pos * inv;
    float c = cosf(f), sn = sinf(f);

    const float* row = g_qkv + (size_t)s * QKVDIM;
    int base = (h * SEQ + s) * HD;

    float q1 = row[h * HD + i], q2 = row[h * HD + i + 32];
    g_q[base + i]      = (q1 * c - q2 * sn) * 0.125f;
    g_q[base + i + 32] = (q2 * c + q1 * sn) * 0.125f;
    float k1 = row[DIM + h * HD + i], k2 = row[DIM + h * HD + i + 32];
    g_k[base + i]      = k1 * c - k2 * sn;
    g_k[base + i + 32] = k2 * c + k1 * sn;
    g_v[base + i]      = row[2 * DIM + h * HD + i];
    g_v[base + i + 32] = row[2 * DIM + h * HD + i + 32];
}

// ============== tensor-core sliding-window attention =========================
#define APITCH 72
#define A_QH 0
#define A_QL (128 * APITCH)
#define A_KH (2 * 128 * APITCH)
#define A_KL (A_KH + 256 * APITCH)
#define A_VH (A_KH + 2 * 256 * APITCH)
#define A_VL (A_VH + 256 * APITCH)
#define ATTN_SMEM ((A_VL + 256 * APITCH) * 2)

__global__ void __launch_bounds__(256, 1) attn_mma_kernel()
{
    extern __shared__ __align__(16) char asm_[];
    __nv_bfloat16* sb = (__nv_bfloat16*)asm_;
    const uint32_t sbase = smem_u32(asm_);

    const int tid = threadIdx.x;
    const int w = tid >> 5;
    const int lane = tid & 31;
    const int h = blockIdx.y;
    const int tile = blockIdx.x;
    const int kbase = tile * 128 - WIN;

    const float* Qg = g_q + ((size_t)h * SEQ + tile * 128) * HD;
    const float* Kg = g_k + (size_t)h * SEQ * HD;
    const float* Vg = g_v + (size_t)h * SEQ * HD;

#pragma unroll
    for (int i = 0; i < 8; i++) {
        int f = tid + i * 256;
        int r = f >> 4, c4 = f & 15;
        float4 v = *(const float4*)(Qg + (size_t)r * HD + c4 * 4);
        uint2 hi, lo;
        split2(v.x, v.y, hi.x, lo.x);
        split2(v.z, v.w, hi.y, lo.y);
        int off = r * APITCH + c4 * 4;
        *(uint2*)(sb + A_QH + off) = hi;
        *(uint2*)(sb + A_QL + off) = lo;
    }
#pragma unroll
    for (int i = 0; i < 16; i++) {
        int f = tid + i * 256;
        int r = f >> 4, c4 = f & 15;
        int key = kbase + r;
        bool ok = (key >= 0) && (key < SEQ);
        float4 kv = make_float4(0.f, 0.f, 0.f, 0.f);
        float4 vv = make_float4(0.f, 0.f, 0.f, 0.f);
        if (ok) {
            kv = *(const float4*)(Kg + (size_t)key * HD + c4 * 4);
            vv = *(const float4*)(Vg + (size_t)key * HD + c4 * 4);
        }
        uint2 hi, lo;
        int off = r * APITCH + c4 * 4;
        split2(kv.x, kv.y, hi.x, lo.x);
        split2(kv.z, kv.w, hi.y, lo.y);
        *(uint2*)(sb + A_KH + off) = hi;
        *(uint2*)(sb + A_KL + off) = lo;
        split2(vv.x, vv.y, hi.x, lo.x);
        split2(vv.z, vv.w, hi.y, lo.y);
        *(uint2*)(sb + A_VH + off) = hi;
        *(uint2*)(sb + A_VL + off) = lo;
    }
    __syncthreads();

    float m0 = -1e30f, m1 = -1e30f, l0 = 0.f, l1 = 0.f;
    float O[8][4];
#pragma unroll
    for (int j = 0; j < 8; j++)
#pragma unroll
        for (int t = 0; t < 4; t++) O[j][t] = 0.f;

    const int q0 = tile * 128 + w * 16 + (lane >> 2);

    for (int c = 0; c < 2; c++) {
        int lo_col = w * 16 - 128 * c;
        int hi_col = lo_col + 143;
        int t_lo = lo_col < 0 ? 0 : (lo_col >> 4);
        int t_hi = (hi_col >> 4) < 7 ? (hi_col >> 4) : 7;

        float S[16][4];
#pragma unroll
        for (int b = 0; b < 16; b++)
#pragma unroll
            for (int t = 0; t < 4; t++) S[b][t] = 0.f;

#pragma unroll
        for (int ks = 0; ks < 4; ks++) {
            uint32_t Ah[4], Al[4];
            uint32_t aoff = (uint32_t)((w * 16 + (lane & 15)) * APITCH + ks * 16 + (lane >> 4) * 8) * 2;
            LDSM4(Ah, sbase + A_QH * 2 + aoff);
            LDSM4(Al, sbase + A_QL * 2 + aoff);
#pragma unroll
            for (int g = 0; g < 8; g++) {
                if (g < t_lo || g > t_hi) continue;
                int quad = lane >> 3, l8 = lane & 7;
                int n = c * 128 + g * 16 + ((quad >> 1) & 1) * 8 + l8;
                int cc = ks * 16 + (quad & 1) * 8;
                uint32_t boff = (uint32_t)(n * APITCH + cc) * 2;
                uint32_t Bh[4], Bl[4];
                LDSM4(Bh, sbase + A_KH * 2 + boff);
                LDSM4(Bl, sbase + A_KL * 2 + boff);
#pragma unroll
                for (int sub = 0; sub < 2; sub++) {
                    float* d = S[g * 2 + sub];
                    MMA_BF16(d, Ah, Bh[2 * sub], Bh[2 * sub + 1]);
                    MMA_BF16(d, Ah, Bl[2 * sub], Bl[2 * sub + 1]);
                    MMA_BF16(d, Al, Bh[2 * sub], Bh[2 * sub + 1]);
                }
            }
        }

        float mc0 = -1e30f, mc1 = -1e30f;
#pragma unroll
        for (int b = 0; b < 16; b++) {
            if ((b >> 1) < t_lo || (b >> 1) > t_hi) continue;
            int k0g = kbase + c * 128 + b * 8 + (lane & 3) * 2;
#pragma unroll
            for (int t = 0; t < 4; t++) {
                int kg = k0g + (t & 1);
                int qq = q0 + (t >> 1) * 8;
                bool ok = (kg >= 0) && (kg < SEQ) && (kg >= qq - WIN) && (kg <= qq + WIN);
                if (!ok) S[b][t] = -1e30f;
            }
            mc0 = fmaxf(mc0, fmaxf(S[b][0], S[b][1]));
            mc1 = fmaxf(mc1, fmaxf(S[b][2], S[b][3]));
        }
        mc0 = fmaxf(mc0, __shfl_xor_sync(0xffffffffu, mc0, 1));
        mc0 = fmaxf(mc0, __shfl_xor_sync(0xffffffffu, mc0, 2));
        mc1 = fmaxf(mc1, __shfl_xor_sync(0xffffffffu, mc1, 1));
        mc1 = fmaxf(mc1, __shfl_xor_sync(0xffffffffu, mc1, 2));

        float nm0 = fmaxf(m0, mc0), nm1 = fmaxf(m1, mc1);
        float f0 = __expf(m0 - nm0), f1 = __expf(m1 - nm1);
        l0 *= f0; l1 *= f1;
#pragma unroll
        for (int j = 0; j < 8; j++) {
            O[j][0] *= f0; O[j][1] *= f0;
            O[j][2] *= f1; O[j][3] *= f1;
        }
        m0 = nm0; m1 = nm1;

        uint32_t Ph[16][2], Pl[16][2];
        float s0 = 0.f, s1 = 0.f;
#pragma unroll
        for (int b = 0; b < 16; b++) {
            if ((b >> 1) < t_lo || (b >> 1) > t_hi) continue;
            float p0 = __expf(S[b][0] - m0), p1 = __expf(S[b][1] - m0);
            float p2 = __expf(S[b][2] - m1), p3 = __expf(S[b][3] - m1);
            s0 += p0 + p1; s1 += p2 + p3;
            split2(p0, p1, Ph[b][0], Pl[b][0]);
            split2(p2, p3, Ph[b][1], Pl[b][1]);
        }
        s0 += __shfl_xor_sync(0xffffffffu, s0, 1);
        s0 += __shfl_xor_sync(0xffffffffu, s0, 2);
        s1 += __shfl_xor_sync(0xffffffffu, s1, 1);
        s1 += __shfl_xor_sync(0xffffffffu, s1, 2);
        l0 += s0; l1 += s1;

#pragma unroll
        for (int kk = 0; kk < 8; kk++) {
            if (kk < t_lo || kk > t_hi) continue;
            uint32_t Aph[4] = {Ph[2 * kk][0], Ph[2 * kk][1], Ph[2 * kk + 1][0], Ph[2 * kk + 1][1]};
            uint32_t Apl[4] = {Pl[2 * kk][0], Pl[2 * kk][1], Pl[2 * kk + 1][0], Pl[2 * kk + 1][1]};
            int krow = c * 128 + kk * 16 + (lane & 7) + ((lane >> 3) & 1) * 8;
#pragma unroll
            for (int g = 0; g < 4; g++) {
                uint32_t voff = (uint32_t)(krow * APITCH + g * 16 + (lane >> 4) * 8) * 2;
                uint32_t Bh[4], Bl[4];
                LDSM4T(Bh, sbase + A_VH * 2 + voff);
                LDSM4T(Bl, sbase + A_VL * 2 + voff);
#pragma unroll
                for (int sub = 0; sub < 2; sub++) {
                    float* d = O[g * 2 + sub];
                    MMA_BF16(d, Aph, Bh[2 * sub], Bh[2 * sub + 1]);
                    MMA_BF16(d, Aph, Bl[2 * sub], Bl[2 * sub + 1]);
                    MMA_BF16(d, Apl, Bh[2 * sub], Bh[2 * sub + 1]);
                }
            }
        }
    }

    float i0 = 1.f / l0, i1 = 1.f / l1;
    float* o0 = g_ao + (size_t)q0 * DIM + h * HD;
    float* o1 = g_ao + (size_t)(q0 + 8) * DIM + h * HD;
#pragma unroll
    for (int j = 0; j < 8; j++) {
        int col = j * 8 + (lane & 3) * 2;
        *(float2*)(o0 + col) = make_float2(O[j][0] * i0, O[j][1] * i0);
        *(float2*)(o1 + col) = make_float2(O[j][2] * i1, O[j][3] * i1);
    }
}

// ---------------- launch -----------------------------------------------------
extern "C" void kernel_launch(void* const* d_in, const int* in_sizes, int n_in,
                              void* d_out, int out_size)
{
    const float* x    = (const float*)d_in[0];
    const int*   pos  = (const int*)  d_in[1];
    const float* wqkv = (const float*)d_in[2];
    const float* wo   = (const float*)d_in[3];
    float*       out  = (float*)d_out;

    float *pqkv, *pao;
    cudaGetSymbolAddress((void**)&pqkv, g_qkv);
    cudaGetSymbolAddress((void**)&pao,  g_ao);

    cudaFuncSetAttribute(gemm_mma_kernel<128>, cudaFuncAttributeMaxDynamicSharedMemorySize, GEMM_SMEM_128);
    cudaFuncSetAttribute(gemm_mma_kernel<64>,  cudaFuncAttributeMaxDynamicSharedMemorySize, GEMM_SMEM_64);
    cudaFuncSetAttribute(attn_mma_kernel, cudaFuncAttributeMaxDynamicSharedMemorySize, ATTN_SMEM);

    // 1) QKV projection: [4096,768] x [2304,768]^T -> [4096,2304]
    gemm_mma_kernel<128><<<dim3(QKVDIM / 128, SEQ / 128), 256, GEMM_SMEM_128>>>(x, wqkv, pqkv, SEQ, QKVDIM, DIM);

    // 2) split + RoPE + transpose
    {
        int total = SEQ * NH * 32;
        rope_split_kernel<<<(total + 255) / 256, 256>>>(pos);
    }

    // 3) sliding-window attention (tensor cores)
    attn_mma_kernel<<<dim3(SEQ / 128, NH), 256, ATTN_SMEM>>>();

    // 4) output projection: [4096,768] x [768,768]^T -> [4096,768]
    //    BM=64 -> 384 CTAs (tail fix)
    gemm_mma_kernel<64><<<dim3(DIM / 128, SEQ / 64), 256, GEMM_SMEM_64>>>(pao, wo, out, SEQ, DIM, DIM);
}